// round 1
// baseline (speedup 1.0000x reference)
#include <cuda_runtime.h>
#include <math.h>
#include <float.h>

#define Bn    8
#define Hn    96
#define Wn    96
#define HWn   9216        // Hn*Wn
#define FCn   768
#define Rn    12
#define Pn    16
#define KSn   13
#define TOPKn 24

// ---------------- scratch (device globals; no allocation) ----------------
__device__ float g_t1[Bn*Rn*HWn];      // after conv1+gelu
__device__ float g_proj[Bn*Rn*HWn];    // after conv2+gelu
__device__ float g_canvas[Bn*Rn*HWn];  // stamped canvas
__device__ float g_occraw[Bn*HWn];
__device__ float g_cavg[Bn*HWn];
__device__ float g_mask[Bn*HWn];
__device__ float g_er[Bn*HWn];
__device__ float g_open[Bn*HWn];
__device__ float g_sup[Bn*HWn];
__device__ float g_occ[Bn*HWn];
__device__ float g_dnorm[Bn*HWn];
__device__ float g_scores[Bn*HWn];
__device__ float g_anch[Bn*HWn];
__device__ float g_mn[24], g_mx[24];   // [3][8]: 0=occraw 1=density 2=cavg
__device__ float g_vals[Bn*TOPKn];
__device__ int   g_idx[Bn*TOPKn];
__device__ int   g_pidx[Bn*TOPKn];

// ---------------- helpers ----------------
__device__ __forceinline__ void ffma2(unsigned long long &acc,
                                      unsigned long long a,
                                      unsigned long long b) {
    asm("fma.rn.f32x2 %0, %1, %2, %0;" : "+l"(acc) : "l"(a), "l"(b));
}
__device__ __forceinline__ unsigned long long dup2(float x) {
    unsigned long long r;
    asm("mov.b64 %0, {%1, %1};" : "=l"(r) : "f"(x));
    return r;
}
__device__ __forceinline__ float2 unpack2(unsigned long long v) {
    float2 r;
    asm("mov.b64 {%0, %1}, %2;" : "=f"(r.x), "=f"(r.y) : "l"(v));
    return r;
}
__device__ __forceinline__ float gelu_exact(float x) {
    return 0.5f * x * (1.0f + erff(x * 0.70710678118654752440f));
}

// ---------------- K1: conv1x1 FC->R + gelu ----------------
// 144 blocks x 256 thr, 2 pixels/thread (float2), r-pair f32x2 packing.
__global__ void __launch_bounds__(256) k_conv1(const float* __restrict__ feat,
                                               const float* __restrict__ w1,
                                               const float* __restrict__ b1) {
    __shared__ float sw[FCn*Rn];   // [c][r], 36KB
    for (int i = threadIdx.x; i < FCn*Rn; i += 256) {
        int c = i / Rn, r = i - c*Rn;
        sw[i] = w1[r*FCn + c];
    }
    __syncthreads();
    int b  = blockIdx.x / 18;
    int p0 = (blockIdx.x % 18) * 512 + threadIdx.x * 2;
    const float* fb = feat + (size_t)b * FCn * HWn + p0;

    unsigned long long acc[12];    // [px0: r-pairs 0..5][px1: 6..11]
#pragma unroll
    for (int j = 0; j < 12; j++) acc[j] = 0ull;

    for (int c0 = 0; c0 < FCn; c0 += 8) {
        float2 xv[8];
#pragma unroll
        for (int u = 0; u < 8; u++)
            xv[u] = *(const float2*)(fb + (size_t)(c0 + u) * HWn);
#pragma unroll
        for (int u = 0; u < 8; u++) {
            unsigned long long d0 = dup2(xv[u].x);
            unsigned long long d1 = dup2(xv[u].y);
            const unsigned long long* wp =
                (const unsigned long long*)(sw + (c0 + u) * Rn);
#pragma unroll
            for (int j = 0; j < 6; j++) {
                unsigned long long w = wp[j];
                ffma2(acc[j],     d0, w);
                ffma2(acc[6 + j], d1, w);
            }
        }
    }
    float* outp = g_t1 + (size_t)b * Rn * HWn + p0;
#pragma unroll
    for (int j = 0; j < 6; j++) {
        float2 a0 = unpack2(acc[j]);       // px0: (r=2j, r=2j+1)
        float2 a1 = unpack2(acc[6 + j]);   // px1
        float bias0 = b1[2*j], bias1 = b1[2*j + 1];
        float2 s0; s0.x = gelu_exact(a0.x + bias0); s0.y = gelu_exact(a1.x + bias0);
        float2 s1; s1.x = gelu_exact(a0.y + bias1); s1.y = gelu_exact(a1.y + bias1);
        *(float2*)(outp + (size_t)(2*j)     * HWn) = s0;
        *(float2*)(outp + (size_t)(2*j + 1) * HWn) = s1;
    }
}

// ---------------- K2: conv3x3 R->R + gelu + occ_raw ----------------
__global__ void __launch_bounds__(256) k_conv2(const float* __restrict__ w2,
                                               const float* __restrict__ b2) {
    __shared__ float tile[Rn][18*18];
    __shared__ float sw2[Rn*Rn*9];  // [(rin*9 + k9)*12 + rout]
    __shared__ float sb2[Rn];
    int b   = blockIdx.z;
    int ty0 = blockIdx.y * 16, tx0 = blockIdx.x * 16;
    for (int i = threadIdx.x; i < Rn*Rn*9; i += 256) {
        int rout = i % 12;
        int rest = i / 12;
        int rin  = rest / 9;
        int k9   = rest % 9;
        sw2[i] = w2[(rout*12 + rin) * 9 + k9];
    }
    if (threadIdx.x < Rn) sb2[threadIdx.x] = b2[threadIdx.x];
    const float* tin = g_t1 + (size_t)b * Rn * HWn;
    for (int i = threadIdx.x; i < Rn*324; i += 256) {
        int ch = i / 324, rem = i - ch*324;
        int yy = rem / 18, xx = rem % 18;
        int gy = ty0 + yy - 1, gx = tx0 + xx - 1;
        float v = 0.0f;
        if (gy >= 0 && gy < Hn && gx >= 0 && gx < Wn)
            v = tin[(size_t)ch * HWn + gy*Wn + gx];
        tile[ch][rem] = v;
    }
    __syncthreads();
    int ty = threadIdx.x / 16, tx = threadIdx.x % 16;
    float acc[12];
#pragma unroll
    for (int r = 0; r < 12; r++) acc[r] = sb2[r];
#pragma unroll
    for (int rin = 0; rin < 12; rin++) {
#pragma unroll
        for (int k9 = 0; k9 < 9; k9++) {
            int ky = k9 / 3, kx = k9 % 3;
            float t = tile[rin][(ty + ky)*18 + tx + kx];
            const float* wr = sw2 + (rin*9 + k9) * 12;
#pragma unroll
            for (int ro = 0; ro < 12; ro++) acc[ro] += t * wr[ro];
        }
    }
    int p = (ty0 + ty)*Wn + tx0 + tx;
    float* pout = g_proj + (size_t)b * Rn * HWn + p;
    float asum = 0.0f;
#pragma unroll
    for (int r = 0; r < 12; r++) {
        float g = gelu_exact(acc[r]);
        pout[(size_t)r * HWn] = g;
        asum += fabsf(g);
    }
    g_occraw[b*HWn + p] = asum * (1.0f / 12.0f);
}

// ---------------- small kernels ----------------
__global__ void k_pre(const float* __restrict__ carrier) {
    int i = blockIdx.x * 256 + threadIdx.x;
    if (i >= Bn*HWn) return;
    int b = i / HWn, p = i - b*HWn;
    int y = p / Wn, x = p - y*Wn;
    const float* cb = carrier + (size_t)b * HWn;
    float s = 0.0f;
    for (int dy = -1; dy <= 1; dy++) {
        int yy = y + dy; if (yy < 0 || yy >= Hn) continue;
        for (int dx = -1; dx <= 1; dx++) {
            int xx = x + dx; if (xx < 0 || xx >= Wn) continue;
            s += fabsf(cb[yy*Wn + xx]);
        }
    }
    g_cavg[i] = s * (1.0f / 9.0f);
}

__global__ void __launch_bounds__(256) k_reduce(const float* __restrict__ density) {
    __shared__ float smn[256], smx[256];
    int a = blockIdx.x / Bn;   // 0=occraw 1=density 2=cavg
    int b = blockIdx.x % Bn;
    const float* src = (a == 0) ? (g_occraw + b*HWn)
                     : (a == 1) ? (density + (size_t)b*HWn)
                                : (g_cavg + b*HWn);
    float mn = FLT_MAX, mx = -FLT_MAX;
    for (int i = threadIdx.x; i < HWn; i += 256) {
        float v = src[i];
        mn = fminf(mn, v); mx = fmaxf(mx, v);
    }
    smn[threadIdx.x] = mn; smx[threadIdx.x] = mx;
    __syncthreads();
    for (int s = 128; s > 0; s >>= 1) {
        if (threadIdx.x < s) {
            smn[threadIdx.x] = fminf(smn[threadIdx.x], smn[threadIdx.x + s]);
            smx[threadIdx.x] = fmaxf(smx[threadIdx.x], smx[threadIdx.x + s]);
        }
        __syncthreads();
    }
    if (threadIdx.x == 0) { g_mn[blockIdx.x] = smn[0]; g_mx[blockIdx.x] = smx[0]; }
}

__global__ void k_mask(const float* __restrict__ density) {
    int i = blockIdx.x * 256 + threadIdx.x;
    if (i >= Bn*HWn) return;
    int b = i / HWn;
    float occ = (g_occraw[i]          - g_mn[b])      / fmaxf(g_mx[b]      - g_mn[b],      1e-6f);
    float dn  = (density[i]           - g_mn[8 + b])  / fmaxf(g_mx[8 + b]  - g_mn[8 + b],  1e-6f);
    float cs  = (g_cavg[i]            - g_mn[16 + b]) / fmaxf(g_mx[16 + b] - g_mn[16 + b], 1e-6f);
    float ev  = 0.8f * cs + 0.2f * dn;
    g_occ[i]   = occ;
    g_dnorm[i] = dn;
    g_mask[i]  = (ev >= 0.28f) ? 1.0f : 0.0f;
}

__device__ __forceinline__ float win3(const float* src, int b, int p, bool ismax) {
    int y = p / Wn, x = p - y*Wn;
    float r = ismax ? -FLT_MAX : FLT_MAX;
    for (int dy = -1; dy <= 1; dy++) {
        int yy = y + dy; if (yy < 0 || yy >= Hn) continue;
        for (int dx = -1; dx <= 1; dx++) {
            int xx = x + dx; if (xx < 0 || xx >= Wn) continue;
            float v = src[(size_t)b*HWn + yy*Wn + xx];
            r = ismax ? fmaxf(r, v) : fminf(r, v);
        }
    }
    return r;
}

__global__ void k_erode() {
    int i = blockIdx.x * 256 + threadIdx.x;
    if (i >= Bn*HWn) return;
    g_er[i] = win3(g_mask, i / HWn, i % HWn, false);
}
__global__ void k_dil1() {
    int i = blockIdx.x * 256 + threadIdx.x;
    if (i >= Bn*HWn) return;
    float v = win3(g_er, i / HWn, i % HWn, true);
    g_open[i] = fminf(fmaxf(v, 0.0f), 1.0f);
}
__global__ void k_dil2() {  // dilation(DIL) + scores + zero canvas/anchor
    int i = blockIdx.x * 256 + threadIdx.x;
    if (i >= Bn*HWn) return;
    int b = i / HWn, p = i - b*HWn;
    float s = fminf(fmaxf(win3(g_open, b, p, true), 0.0f), 1.0f);
    g_sup[i]    = s;
    g_scores[i] = g_occ[i] * s;
    g_anch[i]   = 0.0f;
#pragma unroll
    for (int r = 0; r < Rn; r++)
        g_canvas[((size_t)b*Rn + r) * HWn + p] = 0.0f;
}

// ---------------- NMS + top-k + proto argmax ----------------
__global__ void __launch_bounds__(256) k_topk(const float* __restrict__ proto) {
    __shared__ float sval[HWn];       // 36KB
    __shared__ float rv[256];
    __shared__ int   ri[256];
    int b = blockIdx.x, tid = threadIdx.x;
    const float* sc = g_scores + (size_t)b * HWn;
    for (int p = tid; p < HWn; p += 256) {
        float s  = sc[p];
        float lm = win3(g_scores, b, p, true);
        sval[p] = (s >= lm && s > 0.05f) ? s : 0.0f;
    }
    __syncthreads();
    for (int k = 0; k < TOPKn; k++) {
        float bv = -FLT_MAX; int bi = HWn;
        for (int p = tid; p < HWn; p += 256) {
            float v = sval[p];
            if (v > bv || (v == bv && p < bi)) { bv = v; bi = p; }
        }
        rv[tid] = bv; ri[tid] = bi;
        __syncthreads();
        for (int s = 128; s > 0; s >>= 1) {
            if (tid < s) {
                float ov = rv[tid + s]; int oi = ri[tid + s];
                if (ov > rv[tid] || (ov == rv[tid] && oi < ri[tid])) {
                    rv[tid] = ov; ri[tid] = oi;
                }
            }
            __syncthreads();
        }
        if (tid == 0) {
            g_vals[b*TOPKn + k] = rv[0];
            g_idx[b*TOPKn + k]  = ri[0];
            g_anch[b*HWn + ri[0]] = rv[0];   // anchor_map .set(val)
            sval[ri[0]] = -FLT_MAX;
        }
        __syncthreads();
    }
    // prototype selection (one thread per anchor)
    if (tid < TOPKn) {
        int idx = g_idx[b*TOPKn + tid];
        float f[Rn];
#pragma unroll
        for (int r = 0; r < Rn; r++)
            f[r] = g_proj[((size_t)b*Rn + r) * HWn + idx];
        float best = -FLT_MAX; int bp = 0;
#pragma unroll
        for (int p = 0; p < Pn; p++) {
            float l = 0.0f;
#pragma unroll
            for (int r = 0; r < Rn; r++) l += f[r] * proto[p*Rn + r];
            if (l > best) { best = l; bp = p; }   // first max, like argmax
        }
        g_pidx[b*TOPKn + tid] = bp;
    }
}

// ---------------- stamping ----------------
__device__ __constant__ float c_lenL[4] = {0.4f, 0.7f, 1.0f, 1.25f};
__device__ __constant__ float c_widL[4] = {0.12f, 0.18f, 0.24f, 0.3f};

__global__ void k_stamp(const float* __restrict__ proto) {
    int a = blockIdx.x;               // b*24 + k
    float val = g_vals[a];
    if (val <= 0.0f) return;
    int t = threadIdx.x;
    if (t >= KSn*KSn) return;
    int b   = a / TOPKn;
    int idx = g_idx[a];
    int pi  = g_pidx[a];
    int ys = idx / Wn, xs = idx % Wn;
    int dy = t / KSn, dx = t % KSn;
    int y = ys + dy - KSn/2, x = xs + dx - KSn/2;
    if (y < 0 || y >= Hn || x < 0 || x >= Wn) return;
    // grids like np.linspace (f64 then f32)
    float gx  = (float)(-1.0 + (double)dx * (2.0 / 12.0));
    float gy  = (float)(-1.0 + (double)dy * (2.0 / 12.0));
    float ori = (float)((double)pi * (3.14159265358979323846 / 16.0));
    float ln  = c_lenL[pi & 3];
    float wd  = c_widL[(pi >> 2) & 3];
    float c = cosf(ori), s = sinf(ori);
    float xr =  c * gx + s * gy;
    float yr = -s * gx + c * gy;
    float tx = xr / ln, ty = yr / wd;
    float foot = expf(-(tx*tx) - (ty*ty)) * val;
    float* cv = g_canvas + (size_t)b * Rn * HWn + y*Wn + x;
#pragma unroll
    for (int r = 0; r < Rn; r++)
        atomicAdd(cv + (size_t)r * HWn, proto[pi*Rn + r] * foot);
}

// ---------------- final: (16->12 gelu)->(12->768) fused ----------------
__global__ void __launch_bounds__(256) k_final(const float* __restrict__ w3,
                                               const float* __restrict__ b3,
                                               const float* __restrict__ w4,
                                               const float* __restrict__ b4,
                                               float* __restrict__ outp) {
    __shared__ float swt[Rn*FCn];    // transposed w4: swt[r*768+f] = w4[f*12+r]
    __shared__ float sw3[Rn*16];
    __shared__ float sb3[Rn];
    __shared__ float sb4[FCn];
    for (int i = threadIdx.x; i < Rn*FCn; i += 256) {
        int r = i / FCn, f = i - r*FCn;
        swt[i] = w4[f*Rn + r];
    }
    for (int i = threadIdx.x; i < FCn; i += 256) sb4[i] = b4[i];
    if (threadIdx.x < Rn*16) sw3[threadIdx.x] = w3[threadIdx.x];
    if (threadIdx.x < Rn)    sb3[threadIdx.x] = b3[threadIdx.x];
    __syncthreads();

    int b  = blockIdx.x / 18;
    int p0 = (blockIdx.x % 18) * 512 + threadIdx.x * 2;
    size_t bp = (size_t)b * HWn + p0;

    float2 sup = *(const float2*)(g_sup + bp);
    float2 occ = *(const float2*)(g_occ + bp);
    float2 an  = *(const float2*)(g_anch + bp);
    float2 dn  = *(const float2*)(g_dnorm + bp);

    float in0[16], in1[16];
#pragma unroll
    for (int r = 0; r < Rn; r++) {
        float2 cv = *(const float2*)(g_canvas + ((size_t)b*Rn + r) * HWn + p0);
        in0[r] = cv.x * sup.x;
        in1[r] = cv.y * sup.y;
    }
    in0[12] = occ.x; in1[12] = occ.y;
    in0[13] = sup.x; in1[13] = sup.y;
    in0[14] = an.x;  in1[14] = an.y;
    in0[15] = dn.x;  in1[15] = dn.y;

    unsigned long long md0[Rn], md1[Rn];
#pragma unroll
    for (int r = 0; r < Rn; r++) {
        float m0 = sb3[r], m1 = sb3[r];
#pragma unroll
        for (int j = 0; j < 16; j++) {
            float w = sw3[r*16 + j];
            m0 += in0[j] * w;
            m1 += in1[j] * w;
        }
        md0[r] = dup2(gelu_exact(m0));
        md1[r] = dup2(gelu_exact(m1));
    }

    float* ob = outp + (size_t)b * FCn * HWn + p0;
#pragma unroll 2
    for (int f = 0; f < FCn; f += 2) {
        unsigned long long a0 = *(const unsigned long long*)(sb4 + f); // (b4[f], b4[f+1])
        unsigned long long a1 = a0;
#pragma unroll
        for (int r = 0; r < Rn; r++) {
            unsigned long long w = *(const unsigned long long*)(swt + r*FCn + f);
            ffma2(a0, md0[r], w);   // px0: (out[f], out[f+1])
            ffma2(a1, md1[r], w);   // px1
        }
        float2 u0 = unpack2(a0), u1 = unpack2(a1);
        float2 v0; v0.x = u0.x; v0.y = u1.x;   // row f   : (px0, px1)
        float2 v1; v1.x = u0.y; v1.y = u1.y;   // row f+1 : (px0, px1)
        *(float2*)(ob + (size_t)f       * HWn) = v0;
        *(float2*)(ob + (size_t)(f + 1) * HWn) = v1;
    }
}

// ---------------- launch ----------------
extern "C" void kernel_launch(void* const* d_in, const int* in_sizes, int n_in,
                              void* d_out, int out_size) {
    const float* features = (const float*)d_in[0];
    const float* carrier  = (const float*)d_in[1];
    const float* density  = (const float*)d_in[2];
    const float* w1 = (const float*)d_in[3];
    const float* b1 = (const float*)d_in[4];
    const float* w2 = (const float*)d_in[5];
    const float* b2 = (const float*)d_in[6];
    const float* w3 = (const float*)d_in[7];
    const float* b3 = (const float*)d_in[8];
    const float* w4 = (const float*)d_in[9];
    const float* b4 = (const float*)d_in[10];
    const float* proto = (const float*)d_in[11];
    float* outp = (float*)d_out;

    k_conv1<<<144, 256>>>(features, w1, b1);
    k_conv2<<<dim3(6, 6, 8), 256>>>(w2, b2);
    k_pre<<<288, 256>>>(carrier);
    k_reduce<<<24, 256>>>(density);
    k_mask<<<288, 256>>>(density);
    k_erode<<<288, 256>>>();
    k_dil1<<<288, 256>>>();
    k_dil2<<<288, 256>>>();
    k_topk<<<Bn, 256>>>(proto);
    k_stamp<<<Bn*TOPKn, 192>>>(proto);
    k_final<<<144, 256>>>(w3, b3, w4, b4, outp);
}

// round 3
// speedup vs baseline: 1.5347x; 1.5347x over previous
#include <cuda_runtime.h>
#include <math.h>
#include <float.h>

#define Bn    8
#define Hn    96
#define Wn    96
#define HWn   9216
#define FCn   768
#define Rn    12
#define Pn    16
#define KSn   13
#define TOPKn 24

typedef unsigned long long ull;

// ---------------- scratch (device globals) ----------------
__device__ float g_t1[Bn*Rn*HWn];
__device__ float g_proj[Bn*Rn*HWn];
__device__ float g_canvas[Bn*Rn*HWn];
__device__ float g_occraw[Bn*HWn];
__device__ float g_sup[Bn*HWn];
__device__ float g_occ[Bn*HWn];
__device__ float g_dnorm[Bn*HWn];
__device__ float g_anch[Bn*HWn];
__device__ float g_vals[Bn*TOPKn];
__device__ int   g_idx[Bn*TOPKn];
__device__ int   g_pidx[Bn*TOPKn];

// ---------------- helpers ----------------
__device__ __forceinline__ void ffma2(ull &acc, ull a, ull b) {
    asm("fma.rn.f32x2 %0, %1, %2, %0;" : "+l"(acc) : "l"(a), "l"(b));
}
__device__ __forceinline__ ull dup2(float x) {
    ull r;
    asm("mov.b64 %0, {%1, %1};" : "=l"(r) : "f"(x));
    return r;
}
__device__ __forceinline__ float2 unpack2(ull v) {
    float2 r;
    asm("mov.b64 {%0, %1}, %2;" : "=f"(r.x), "=f"(r.y) : "l"(v));
    return r;
}
__device__ __forceinline__ float gelu_exact(float x) {
    return 0.5f * x * (1.0f + erff(x * 0.70710678118654752440f));
}

// ---------------- K1: conv1x1 FC->R + gelu ----------------
__global__ void __launch_bounds__(256, 2) k_conv1(const float* __restrict__ feat,
                                                  const float* __restrict__ w1,
                                                  const float* __restrict__ b1) {
    __shared__ __align__(16) float sw[FCn*Rn];   // [c][r] contiguous 12 floats/channel
    for (int i = threadIdx.x; i < FCn*Rn; i += 256) {
        int c = i / Rn, r = i - c*Rn;
        sw[i] = w1[r*FCn + c];
    }
    __syncthreads();
    int b = blockIdx.x / 36;
    int p = (blockIdx.x % 36) * 256 + threadIdx.x;
    const float* fb = feat + (size_t)b * FCn * HWn + p;

    ull acc[6];
#pragma unroll
    for (int j = 0; j < 6; j++) acc[j] = 0ull;

    const ulonglong2* wv = (const ulonglong2*)sw;  // 3 per channel

    float cur[8], nxt[8];
#pragma unroll
    for (int u = 0; u < 8; u++) cur[u] = fb[(size_t)u * HWn];
    const float* fc = fb + (size_t)8 * HWn;

    for (int g = 0; g < 95; g++) {
#pragma unroll
        for (int u = 0; u < 8; u++) nxt[u] = fc[(size_t)u * HWn];
        fc += (size_t)8 * HWn;
        int cb = g * 8;
#pragma unroll
        for (int u = 0; u < 8; u++) {
            ull d = dup2(cur[u]);
            const ulonglong2* w = wv + (cb + u) * 3;
            ulonglong2 w0 = w[0], w1v = w[1], w2v = w[2];
            ffma2(acc[0], d, w0.x);  ffma2(acc[1], d, w0.y);
            ffma2(acc[2], d, w1v.x); ffma2(acc[3], d, w1v.y);
            ffma2(acc[4], d, w2v.x); ffma2(acc[5], d, w2v.y);
        }
#pragma unroll
        for (int u = 0; u < 8; u++) cur[u] = nxt[u];
    }
#pragma unroll
    for (int u = 0; u < 8; u++) {
        ull d = dup2(cur[u]);
        const ulonglong2* w = wv + (760 + u) * 3;
        ulonglong2 w0 = w[0], w1v = w[1], w2v = w[2];
        ffma2(acc[0], d, w0.x);  ffma2(acc[1], d, w0.y);
        ffma2(acc[2], d, w1v.x); ffma2(acc[3], d, w1v.y);
        ffma2(acc[4], d, w2v.x); ffma2(acc[5], d, w2v.y);
    }

    float* op = g_t1 + (size_t)b * Rn * HWn + p;
#pragma unroll
    for (int j = 0; j < 6; j++) {
        float2 a = unpack2(acc[j]);
        op[(size_t)(2*j)     * HWn] = gelu_exact(a.x + __ldg(b1 + 2*j));
        op[(size_t)(2*j + 1) * HWn] = gelu_exact(a.y + __ldg(b1 + 2*j + 1));
    }
}

// ---------------- K2: conv3x3 R->R + gelu + occ_raw + canvas zero ----------------
__global__ void __launch_bounds__(256) k_conv2(const float* __restrict__ w2,
                                               const float* __restrict__ b2) {
    __shared__ float tile[Rn][18*18];
    __shared__ __align__(16) float sw2[Rn*Rn*9];  // [(rin*9+k9)*12 + rout]
    __shared__ __align__(16) float sb2[Rn];
    int b   = blockIdx.z;
    int ty0 = blockIdx.y * 16, tx0 = blockIdx.x * 16;
    for (int i = threadIdx.x; i < Rn*Rn*9; i += 256) {
        int rout = i % 12;
        int rest = i / 12;
        int rin  = rest / 9;
        int k9   = rest % 9;
        sw2[i] = w2[(rout*12 + rin) * 9 + k9];
    }
    if (threadIdx.x < Rn) sb2[threadIdx.x] = b2[threadIdx.x];
    const float* tin = g_t1 + (size_t)b * Rn * HWn;
    for (int i = threadIdx.x; i < Rn*324; i += 256) {
        int ch = i / 324, rem = i - ch*324;
        int yy = rem / 18, xx = rem % 18;
        int gy = ty0 + yy - 1, gx = tx0 + xx - 1;
        float v = 0.0f;
        if (gy >= 0 && gy < Hn && gx >= 0 && gx < Wn)
            v = tin[(size_t)ch * HWn + gy*Wn + gx];
        tile[ch][rem] = v;
    }
    __syncthreads();
    int ty = threadIdx.x / 16, tx = threadIdx.x % 16;
    ull acc[6];
    {
        const ull* bb = (const ull*)sb2;
#pragma unroll
        for (int j = 0; j < 6; j++) acc[j] = bb[j];
    }
    const ulonglong2* wv = (const ulonglong2*)sw2;
#pragma unroll
    for (int rin = 0; rin < 12; rin++) {
#pragma unroll
        for (int k9 = 0; k9 < 9; k9++) {
            int ky = k9 / 3, kx = k9 % 3;
            ull d = dup2(tile[rin][(ty + ky)*18 + tx + kx]);
            const ulonglong2* w = wv + (rin*9 + k9) * 3;
            ulonglong2 w0 = w[0], w1v = w[1], w2v = w[2];
            ffma2(acc[0], d, w0.x);  ffma2(acc[1], d, w0.y);
            ffma2(acc[2], d, w1v.x); ffma2(acc[3], d, w1v.y);
            ffma2(acc[4], d, w2v.x); ffma2(acc[5], d, w2v.y);
        }
    }
    int p = (ty0 + ty)*Wn + tx0 + tx;
    float* pout = g_proj + (size_t)b * Rn * HWn + p;
    float* cz   = g_canvas + (size_t)b * Rn * HWn + p;
    float asum = 0.0f;
#pragma unroll
    for (int j = 0; j < 6; j++) {
        float2 a = unpack2(acc[j]);
        float g0 = gelu_exact(a.x), g1 = gelu_exact(a.y);
        pout[(size_t)(2*j)     * HWn] = g0;
        pout[(size_t)(2*j + 1) * HWn] = g1;
        cz[(size_t)(2*j)     * HWn] = 0.0f;
        cz[(size_t)(2*j + 1) * HWn] = 0.0f;
        asum += fabsf(g0) + fabsf(g1);
    }
    g_occraw[b*HWn + p] = asum * (1.0f / 12.0f);
}

// ---------------- fused support / NMS / top-k / proto (1 block per batch) ----------------
__device__ __forceinline__ float win3max_s(const float* S, int y, int x) {
    float r = -FLT_MAX;
#pragma unroll
    for (int dy = -1; dy <= 1; dy++) {
        int yy = y + dy; if (yy < 0 || yy >= Hn) continue;
#pragma unroll
        for (int dx = -1; dx <= 1; dx++) {
            int xx = x + dx; if (xx < 0 || xx >= Wn) continue;
            r = fmaxf(r, S[yy*Wn + xx]);
        }
    }
    return r;
}
__device__ __forceinline__ float win3min_s(const float* S, int y, int x) {
    float r = FLT_MAX;
#pragma unroll
    for (int dy = -1; dy <= 1; dy++) {
        int yy = y + dy; if (yy < 0 || yy >= Hn) continue;
#pragma unroll
        for (int dx = -1; dx <= 1; dx++) {
            int xx = x + dx; if (xx < 0 || xx >= Wn) continue;
            r = fminf(r, S[yy*Wn + xx]);
        }
    }
    return r;
}
__device__ __forceinline__ float win3sum_s(const float* S, int y, int x) {
    float r = 0.0f;
#pragma unroll
    for (int dy = -1; dy <= 1; dy++) {
        int yy = y + dy; if (yy < 0 || yy >= Hn) continue;
#pragma unroll
        for (int dx = -1; dx <= 1; dx++) {
            int xx = x + dx; if (xx < 0 || xx >= Wn) continue;
            r += S[yy*Wn + xx];
        }
    }
    return r;
}

__global__ void __launch_bounds__(1024) k_fused(const float* __restrict__ carrier,
                                                const float* __restrict__ density,
                                                const float* __restrict__ proto) {
    __shared__ float S[HWn];
    __shared__ float smn[32], smx[32];
    __shared__ float rv[32];
    __shared__ int   ri[32];
    __shared__ float sprot[Pn*Rn];
    __shared__ float s_val[TOPKn];
    __shared__ int   s_idx[TOPKn];
    __shared__ int   s_bi;

    int b = blockIdx.x, tid = threadIdx.x;
    int lane = tid & 31, warp = tid >> 5;
    const size_t base = (size_t)b * HWn;

    if (tid < Pn*Rn) sprot[tid] = proto[tid];

    float dreg[9], oreg[9];
    float dmn = FLT_MAX, dmx = -FLT_MAX, omn = FLT_MAX, omx = -FLT_MAX;
#pragma unroll
    for (int j = 0; j < 9; j++) {
        int px = tid + j*1024;
        float d = density[base + px];
        float o = g_occraw[base + px];
        dreg[j] = d; oreg[j] = o;
        dmn = fminf(dmn, d); dmx = fmaxf(dmx, d);
        omn = fminf(omn, o); omx = fmaxf(omx, o);
        S[px] = fabsf(carrier[base + px]);
    }
#pragma unroll
    for (int off = 16; off; off >>= 1) {
        dmn = fminf(dmn, __shfl_down_sync(0xffffffffu, dmn, off));
        dmx = fmaxf(dmx, __shfl_down_sync(0xffffffffu, dmx, off));
        omn = fminf(omn, __shfl_down_sync(0xffffffffu, omn, off));
        omx = fmaxf(omx, __shfl_down_sync(0xffffffffu, omx, off));
    }
    if (!lane) { smn[warp] = dmn; smx[warp] = dmx; rv[warp] = omn; ri[warp] = __float_as_int(omx); }
    __syncthreads();
    if (tid < 32) {
        float a = smn[lane], c = smx[lane], e = rv[lane], f = __int_as_float(ri[lane]);
#pragma unroll
        for (int off = 16; off; off >>= 1) {
            a = fminf(a, __shfl_down_sync(0xffffffffu, a, off));
            c = fmaxf(c, __shfl_down_sync(0xffffffffu, c, off));
            e = fminf(e, __shfl_down_sync(0xffffffffu, e, off));
            f = fmaxf(f, __shfl_down_sync(0xffffffffu, f, off));
        }
        if (!lane) { smn[0] = a; smx[0] = c; rv[0] = e; ri[0] = __float_as_int(f); }
    }
    __syncthreads();
    dmn = smn[0]; dmx = smx[0]; omn = rv[0]; omx = __int_as_float(ri[0]);
    __syncthreads();

    float cav[9];
    float cmn = FLT_MAX, cmx = -FLT_MAX;
#pragma unroll
    for (int j = 0; j < 9; j++) {
        int px = tid + j*1024;
        int y = px / Wn, x = px - y*Wn;
        float v = win3sum_s(S, y, x) * (1.0f / 9.0f);
        cav[j] = v;
        cmn = fminf(cmn, v); cmx = fmaxf(cmx, v);
    }
#pragma unroll
    for (int off = 16; off; off >>= 1) {
        cmn = fminf(cmn, __shfl_down_sync(0xffffffffu, cmn, off));
        cmx = fmaxf(cmx, __shfl_down_sync(0xffffffffu, cmx, off));
    }
    if (!lane) { smn[warp] = cmn; smx[warp] = cmx; }
    __syncthreads();
    if (tid < 32) {
        float a = smn[lane], c = smx[lane];
#pragma unroll
        for (int off = 16; off; off >>= 1) {
            a = fminf(a, __shfl_down_sync(0xffffffffu, a, off));
            c = fmaxf(c, __shfl_down_sync(0xffffffffu, c, off));
        }
        if (!lane) { smn[0] = a; smx[0] = c; }
    }
    __syncthreads();
    cmn = smn[0]; cmx = smx[0];

    float dinv = 1.0f / fmaxf(dmx - dmn, 1e-6f);
    float oinv = 1.0f / fmaxf(omx - omn, 1e-6f);
    float cinv = 1.0f / fmaxf(cmx - cmn, 1e-6f);

    float occ[9], mval[9];
#pragma unroll
    for (int j = 0; j < 9; j++) {
        int px = tid + j*1024;
        float dn = (dreg[j] - dmn) * dinv;
        float oc = (oreg[j] - omn) * oinv;
        float cs = (cav[j] - cmn) * cinv;
        g_dnorm[base + px] = dn;
        g_occ[base + px] = oc;
        occ[j] = oc;
        float ev = 0.8f * cs + 0.2f * dn;
        mval[j] = (ev >= 0.28f) ? 1.0f : 0.0f;
    }
    __syncthreads();
#pragma unroll
    for (int j = 0; j < 9; j++) S[tid + j*1024] = mval[j];
    __syncthreads();
    float er[9];
#pragma unroll
    for (int j = 0; j < 9; j++) {
        int px = tid + j*1024;
        er[j] = win3min_s(S, px / Wn, px % Wn);
    }
    __syncthreads();
#pragma unroll
    for (int j = 0; j < 9; j++) S[tid + j*1024] = er[j];
    __syncthreads();
    float op[9];
#pragma unroll
    for (int j = 0; j < 9; j++) {
        int px = tid + j*1024;
        op[j] = fminf(fmaxf(win3max_s(S, px / Wn, px % Wn), 0.0f), 1.0f);
    }
    __syncthreads();
#pragma unroll
    for (int j = 0; j < 9; j++) S[tid + j*1024] = op[j];
    __syncthreads();
    float sc[9];
#pragma unroll
    for (int j = 0; j < 9; j++) {
        int px = tid + j*1024;
        float sp = fminf(fmaxf(win3max_s(S, px / Wn, px % Wn), 0.0f), 1.0f);
        g_sup[base + px] = sp;
        sc[j] = occ[j] * sp;
    }
    __syncthreads();
#pragma unroll
    for (int j = 0; j < 9; j++) S[tid + j*1024] = sc[j];
    __syncthreads();
    float masked[9];
#pragma unroll
    for (int j = 0; j < 9; j++) {
        int px = tid + j*1024;
        float lm = win3max_s(S, px / Wn, px % Wn);
        masked[j] = (sc[j] >= lm && sc[j] > 0.05f) ? sc[j] : 0.0f;
        g_anch[base + px] = 0.0f;
    }
    __syncthreads();

    for (int k = 0; k < TOPKn; k++) {
        float v = -FLT_MAX; int bi = 0x7fffffff;
#pragma unroll
        for (int j = 0; j < 9; j++) {
            float m = masked[j]; int ix = tid + j*1024;
            if (m > v || (m == v && ix < bi)) { v = m; bi = ix; }
        }
#pragma unroll
        for (int off = 16; off; off >>= 1) {
            float ov = __shfl_down_sync(0xffffffffu, v, off);
            int   oi = __shfl_down_sync(0xffffffffu, bi, off);
            if (ov > v || (ov == v && oi < bi)) { v = ov; bi = oi; }
        }
        if (!lane) { rv[warp] = v; ri[warp] = bi; }
        __syncthreads();
        if (tid < 32) {
            v = rv[lane]; bi = ri[lane];
#pragma unroll
            for (int off = 16; off; off >>= 1) {
                float ov = __shfl_down_sync(0xffffffffu, v, off);
                int   oi = __shfl_down_sync(0xffffffffu, bi, off);
                if (ov > v || (ov == v && oi < bi)) { v = ov; bi = oi; }
            }
            if (!lane) { s_val[k] = v; s_idx[k] = bi; s_bi = bi; }
        }
        __syncthreads();
        int win = s_bi;
        if ((win & 1023) == tid) masked[win >> 10] = -FLT_MAX;
    }
    __syncthreads();

    if (tid < TOPKn) {
        float v = s_val[tid];
        int   ix = s_idx[tid];
        g_vals[b*TOPKn + tid] = v;
        g_idx [b*TOPKn + tid] = ix;
        g_anch[base + ix] = v;
        float f[Rn];
#pragma unroll
        for (int r = 0; r < Rn; r++)
            f[r] = g_proj[((size_t)b*Rn + r) * HWn + ix];
        float best = -FLT_MAX; int bp = 0;
#pragma unroll
        for (int p = 0; p < Pn; p++) {
            float l = 0.0f;
#pragma unroll
            for (int r = 0; r < Rn; r++) l += f[r] * sprot[p*Rn + r];
            if (l > best) { best = l; bp = p; }
        }
        g_pidx[b*TOPKn + tid] = bp;
    }
}

// ---------------- stamping ----------------
__device__ __constant__ float c_lenL[4] = {0.4f, 0.7f, 1.0f, 1.25f};
__device__ __constant__ float c_widL[4] = {0.12f, 0.18f, 0.24f, 0.3f};

__global__ void k_stamp(const float* __restrict__ proto) {
    int a = blockIdx.x;               // b*24 + k
    float val = g_vals[a];
    if (val <= 0.0f) return;
    int t = threadIdx.x;
    if (t >= KSn*KSn) return;
    int b   = a / TOPKn;
    int idx = g_idx[a];
    int pi  = g_pidx[a];
    int ys = idx / Wn, xs = idx % Wn;
    int dy = t / KSn, dx = t % KSn;
    int y = ys + dy - KSn/2, x = xs + dx - KSn/2;
    if (y < 0 || y >= Hn || x < 0 || x >= Wn) return;
    float gx  = (float)(-1.0 + (double)dx * (2.0 / 12.0));
    float gy  = (float)(-1.0 + (double)dy * (2.0 / 12.0));
    float ori = (float)((double)pi * (3.14159265358979323846 / 16.0));
    float ln  = c_lenL[pi & 3];
    float wd  = c_widL[(pi >> 2) & 3];
    float c = cosf(ori), s = sinf(ori);
    float xr =  c * gx + s * gy;
    float yr = -s * gx + c * gy;
    float tx = xr / ln, ty = yr / wd;
    float foot = expf(-(tx*tx) - (ty*ty)) * val;
    float* cv = g_canvas + (size_t)b * Rn * HWn + y*Wn + x;
#pragma unroll
    for (int r = 0; r < Rn; r++)
        atomicAdd(cv + (size_t)r * HWn, proto[pi*Rn + r] * foot);
}

// ---------------- final: (16->12 gelu)->(12->768) fused ----------------
__global__ void __launch_bounds__(128, 4) k_final(const float* __restrict__ w3,
                                                  const float* __restrict__ b3,
                                                  const float* __restrict__ w4,
                                                  const float* __restrict__ b4,
                                                  float* __restrict__ outp) {
    __shared__ __align__(16) ull wint[384*12];  // [(f-pair)][r] = (w4[2fp][r], w4[2fp+1][r])
    __shared__ ull bp4[384];                    // (b4[2fp], b4[2fp+1])
    __shared__ float sw3[Rn*16];
    __shared__ float sb3[Rn];
    {
        float* wf = (float*)wint;
        for (int i = threadIdx.x; i < FCn*Rn; i += 128) {
            int f = i / Rn, r = i - f*Rn;
            wf[(f >> 1)*24 + r*2 + (f & 1)] = w4[f*Rn + r];
        }
        float* bf = (float*)bp4;
        for (int i = threadIdx.x; i < FCn; i += 128) bf[i] = b4[i];
        for (int i = threadIdx.x; i < Rn*16; i += 128) sw3[i] = w3[i];   // FIXED: was guarded by tid<192 with 128 threads
        for (int i = threadIdx.x; i < Rn;    i += 128) sb3[i] = b3[i];
    }
    __syncthreads();

    int b  = blockIdx.x / 36;
    int p0 = (blockIdx.x % 36) * 256 + threadIdx.x * 2;
    size_t bpx = (size_t)b * HWn + p0;

    float2 sup = *(const float2*)(g_sup + bpx);
    float2 occ = *(const float2*)(g_occ + bpx);
    float2 an  = *(const float2*)(g_anch + bpx);
    float2 dn  = *(const float2*)(g_dnorm + bpx);

    float in0[16], in1[16];
#pragma unroll
    for (int r = 0; r < Rn; r++) {
        float2 cv = *(const float2*)(g_canvas + ((size_t)b*Rn + r) * HWn + p0);
        in0[r] = cv.x * sup.x;
        in1[r] = cv.y * sup.y;
    }
    in0[12] = occ.x; in1[12] = occ.y;
    in0[13] = sup.x; in1[13] = sup.y;
    in0[14] = an.x;  in1[14] = an.y;
    in0[15] = dn.x;  in1[15] = dn.y;

    ull md0[Rn], md1[Rn];
#pragma unroll
    for (int r = 0; r < Rn; r++) {
        float m0 = sb3[r], m1 = sb3[r];
#pragma unroll
        for (int j = 0; j < 16; j++) {
            float w = sw3[r*16 + j];
            m0 += in0[j] * w;
            m1 += in1[j] * w;
        }
        md0[r] = dup2(gelu_exact(m0));
        md1[r] = dup2(gelu_exact(m1));
    }

    float* ob = outp + (size_t)b * FCn * HWn + p0;
    const ulonglong2* wv = (const ulonglong2*)wint;
#pragma unroll 2
    for (int fp = 0; fp < 384; fp++) {
        ull a0 = bp4[fp];
        ull a1 = a0;
        const ulonglong2* w = wv + fp*6;
#pragma unroll
        for (int q = 0; q < 6; q++) {
            ulonglong2 wq = w[q];
            ffma2(a0, md0[2*q],     wq.x);
            ffma2(a1, md1[2*q],     wq.x);
            ffma2(a0, md0[2*q + 1], wq.y);
            ffma2(a1, md1[2*q + 1], wq.y);
        }
        float2 u0 = unpack2(a0), u1 = unpack2(a1);
        float2 v0; v0.x = u0.x; v0.y = u1.x;
        float2 v1; v1.x = u0.y; v1.y = u1.y;
        *(float2*)(ob + (size_t)(2*fp)     * HWn) = v0;
        *(float2*)(ob + (size_t)(2*fp + 1) * HWn) = v1;
    }
}

// ---------------- launch ----------------
extern "C" void kernel_launch(void* const* d_in, const int* in_sizes, int n_in,
                              void* d_out, int out_size) {
    const float* features = (const float*)d_in[0];
    const float* carrier  = (const float*)d_in[1];
    const float* density  = (const float*)d_in[2];
    const float* w1 = (const float*)d_in[3];
    const float* b1 = (const float*)d_in[4];
    const float* w2 = (const float*)d_in[5];
    const float* b2 = (const float*)d_in[6];
    const float* w3 = (const float*)d_in[7];
    const float* b3 = (const float*)d_in[8];
    const float* w4 = (const float*)d_in[9];
    const float* b4 = (const float*)d_in[10];
    const float* proto = (const float*)d_in[11];
    float* outp = (float*)d_out;

    k_conv1<<<288, 256>>>(features, w1, b1);
    k_conv2<<<dim3(6, 6, 8), 256>>>(w2, b2);
    k_fused<<<Bn, 1024>>>(carrier, density, proto);
    k_stamp<<<Bn*TOPKn, 192>>>(proto);
    k_final<<<288, 128>>>(w3, b3, w4, b4, outp);
}

// round 4
// speedup vs baseline: 1.6259x; 1.0594x over previous
#include <cuda_runtime.h>
#include <math.h>
#include <float.h>

#define Bn    8
#define Hn    96
#define Wn    96
#define HWn   9216
#define FCn   768
#define Rn    12
#define Pn    16
#define KSn   13
#define TOPKn 24

typedef unsigned long long ull;

// ---------------- scratch (device globals) ----------------
__device__ float g_t1[Bn*Rn*HWn];
__device__ float g_proj[Bn*Rn*HWn];
__device__ float g_canvas[Bn*Rn*HWn];
__device__ float g_occraw[Bn*HWn];
__device__ float g_sup[Bn*HWn];
__device__ float g_occ[Bn*HWn];
__device__ float g_dnorm[Bn*HWn];
__device__ float g_anch[Bn*HWn];

// ---------------- helpers ----------------
__device__ __forceinline__ void ffma2(ull &acc, ull a, ull b) {
    asm("fma.rn.f32x2 %0, %1, %2, %0;" : "+l"(acc) : "l"(a), "l"(b));
}
__device__ __forceinline__ ull dup2(float x) {
    ull r;
    asm("mov.b64 %0, {%1, %1};" : "=l"(r) : "f"(x));
    return r;
}
__device__ __forceinline__ float2 unpack2(ull v) {
    float2 r;
    asm("mov.b64 {%0, %1}, %2;" : "=f"(r.x), "=f"(r.y) : "l"(v));
    return r;
}
__device__ __forceinline__ float gelu_exact(float x) {
    return 0.5f * x * (1.0f + erff(x * 0.70710678118654752440f));
}

// ---------------- K1: conv1x1 FC->R + gelu (3-buffer deep LDG pipeline) ----------------
__global__ void __launch_bounds__(256, 2) k_conv1(const float* __restrict__ feat,
                                                  const float* __restrict__ w1,
                                                  const float* __restrict__ b1) {
    __shared__ __align__(16) float sw[FCn*Rn];   // [c][r] contiguous 12 floats/channel
    for (int i = threadIdx.x; i < FCn*Rn; i += 256) {
        int c = i / Rn, r = i - c*Rn;
        sw[i] = w1[r*FCn + c];
    }
    __syncthreads();
    int b = blockIdx.x / 36;
    int p = (blockIdx.x % 36) * 256 + threadIdx.x;
    const float* fb = feat + (size_t)b * FCn * HWn + p;

    ull acc[6];
#pragma unroll
    for (int j = 0; j < 6; j++) acc[j] = 0ull;

    const ulonglong2* wv = (const ulonglong2*)sw;  // 3 per channel

#define LOAD8(X, CH) do { \
    _Pragma("unroll") \
    for (int u_ = 0; u_ < 8; u_++) X[u_] = fb[(size_t)((CH) + u_) * HWn]; \
} while (0)
#define COMP8(X, CH) do { \
    _Pragma("unroll") \
    for (int u_ = 0; u_ < 8; u_++) { \
        ull d_ = dup2(X[u_]); \
        const ulonglong2* w_ = wv + ((CH) + u_) * 3; \
        ulonglong2 q0 = w_[0], q1 = w_[1], q2 = w_[2]; \
        ffma2(acc[0], d_, q0.x); ffma2(acc[1], d_, q0.y); \
        ffma2(acc[2], d_, q1.x); ffma2(acc[3], d_, q1.y); \
        ffma2(acc[4], d_, q2.x); ffma2(acc[5], d_, q2.y); \
    } \
} while (0)

    float A[8], B[8], C[8];
    LOAD8(A, 0); LOAD8(B, 8); LOAD8(C, 16);
    int cb = 0;
#pragma unroll 1
    for (int it = 0; it < 31; it++) {
        COMP8(A, cb);      LOAD8(A, cb + 24);
        COMP8(B, cb + 8);  LOAD8(B, cb + 32);
        COMP8(C, cb + 16); LOAD8(C, cb + 40);
        cb += 24;
    }
    // cb == 744: A=744..751, B=752..759, C=760..767 already loaded
    COMP8(A, 744); COMP8(B, 752); COMP8(C, 760);
#undef LOAD8
#undef COMP8

    float* op = g_t1 + (size_t)b * Rn * HWn + p;
#pragma unroll
    for (int j = 0; j < 6; j++) {
        float2 a = unpack2(acc[j]);
        op[(size_t)(2*j)     * HWn] = gelu_exact(a.x + __ldg(b1 + 2*j));
        op[(size_t)(2*j + 1) * HWn] = gelu_exact(a.y + __ldg(b1 + 2*j + 1));
    }
}

// ---------------- K2: conv3x3 R->R + gelu + occ_raw + canvas zero ----------------
__global__ void __launch_bounds__(256) k_conv2(const float* __restrict__ w2,
                                               const float* __restrict__ b2) {
    __shared__ float tile[Rn][18*18];
    __shared__ __align__(16) float sw2[Rn*Rn*9];
    __shared__ __align__(16) float sb2[Rn];
    int b   = blockIdx.z;
    int ty0 = blockIdx.y * 16, tx0 = blockIdx.x * 16;
    for (int i = threadIdx.x; i < Rn*Rn*9; i += 256) {
        int rout = i % 12;
        int rest = i / 12;
        int rin  = rest / 9;
        int k9   = rest % 9;
        sw2[i] = w2[(rout*12 + rin) * 9 + k9];
    }
    if (threadIdx.x < Rn) sb2[threadIdx.x] = b2[threadIdx.x];
    const float* tin = g_t1 + (size_t)b * Rn * HWn;
    for (int i = threadIdx.x; i < Rn*324; i += 256) {
        int ch = i / 324, rem = i - ch*324;
        int yy = rem / 18, xx = rem % 18;
        int gy = ty0 + yy - 1, gx = tx0 + xx - 1;
        float v = 0.0f;
        if (gy >= 0 && gy < Hn && gx >= 0 && gx < Wn)
            v = tin[(size_t)ch * HWn + gy*Wn + gx];
        tile[ch][rem] = v;
    }
    __syncthreads();
    int ty = threadIdx.x / 16, tx = threadIdx.x % 16;
    ull acc[6];
    {
        const ull* bb = (const ull*)sb2;
#pragma unroll
        for (int j = 0; j < 6; j++) acc[j] = bb[j];
    }
    const ulonglong2* wv = (const ulonglong2*)sw2;
#pragma unroll
    for (int rin = 0; rin < 12; rin++) {
#pragma unroll
        for (int k9 = 0; k9 < 9; k9++) {
            int ky = k9 / 3, kx = k9 % 3;
            ull d = dup2(tile[rin][(ty + ky)*18 + tx + kx]);
            const ulonglong2* w = wv + (rin*9 + k9) * 3;
            ulonglong2 w0 = w[0], w1v = w[1], w2v = w[2];
            ffma2(acc[0], d, w0.x);  ffma2(acc[1], d, w0.y);
            ffma2(acc[2], d, w1v.x); ffma2(acc[3], d, w1v.y);
            ffma2(acc[4], d, w2v.x); ffma2(acc[5], d, w2v.y);
        }
    }
    int p = (ty0 + ty)*Wn + tx0 + tx;
    float* pout = g_proj + (size_t)b * Rn * HWn + p;
    float* cz   = g_canvas + (size_t)b * Rn * HWn + p;
    float asum = 0.0f;
#pragma unroll
    for (int j = 0; j < 6; j++) {
        float2 a = unpack2(acc[j]);
        float g0 = gelu_exact(a.x), g1 = gelu_exact(a.y);
        pout[(size_t)(2*j)     * HWn] = g0;
        pout[(size_t)(2*j + 1) * HWn] = g1;
        cz[(size_t)(2*j)     * HWn] = 0.0f;
        cz[(size_t)(2*j + 1) * HWn] = 0.0f;
        asum += fabsf(g0) + fabsf(g1);
    }
    g_occraw[b*HWn + p] = asum * (1.0f / 12.0f);
}

// ---------------- fused support/NMS/top-k/proto/stamp (1 block per batch) ----------------
__device__ __forceinline__ float win3max_s(const float* S, int y, int x) {
    float r = -FLT_MAX;
#pragma unroll
    for (int dy = -1; dy <= 1; dy++) {
        int yy = y + dy; if (yy < 0 || yy >= Hn) continue;
#pragma unroll
        for (int dx = -1; dx <= 1; dx++) {
            int xx = x + dx; if (xx < 0 || xx >= Wn) continue;
            r = fmaxf(r, S[yy*Wn + xx]);
        }
    }
    return r;
}
__device__ __forceinline__ float win3min_s(const float* S, int y, int x) {
    float r = FLT_MAX;
#pragma unroll
    for (int dy = -1; dy <= 1; dy++) {
        int yy = y + dy; if (yy < 0 || yy >= Hn) continue;
#pragma unroll
        for (int dx = -1; dx <= 1; dx++) {
            int xx = x + dx; if (xx < 0 || xx >= Wn) continue;
            r = fminf(r, S[yy*Wn + xx]);
        }
    }
    return r;
}
__device__ __forceinline__ float win3sum_s(const float* S, int y, int x) {
    float r = 0.0f;
#pragma unroll
    for (int dy = -1; dy <= 1; dy++) {
        int yy = y + dy; if (yy < 0 || yy >= Hn) continue;
#pragma unroll
        for (int dx = -1; dx <= 1; dx++) {
            int xx = x + dx; if (xx < 0 || xx >= Wn) continue;
            r += S[yy*Wn + xx];
        }
    }
    return r;
}

__device__ __constant__ float c_lenL[4] = {0.4f, 0.7f, 1.0f, 1.25f};
__device__ __constant__ float c_widL[4] = {0.12f, 0.18f, 0.24f, 0.3f};

__global__ void __launch_bounds__(1024) k_fused(const float* __restrict__ carrier,
                                                const float* __restrict__ density,
                                                const float* __restrict__ proto) {
    __shared__ float S[HWn];
    __shared__ float smn[32], smx[32];
    __shared__ float rv[32];
    __shared__ int   ri[32];
    __shared__ float sprot[Pn*Rn];
    __shared__ float s_val[TOPKn];
    __shared__ int   s_idx[TOPKn];
    __shared__ int   spidx[TOPKn];
    __shared__ int   s_bi;

    int b = blockIdx.x, tid = threadIdx.x;
    int lane = tid & 31, warp = tid >> 5;
    const size_t base = (size_t)b * HWn;

    if (tid < Pn*Rn) sprot[tid] = proto[tid];

    float dreg[9], oreg[9];
    float dmn = FLT_MAX, dmx = -FLT_MAX, omn = FLT_MAX, omx = -FLT_MAX;
#pragma unroll
    for (int j = 0; j < 9; j++) {
        int px = tid + j*1024;
        float d = density[base + px];
        float o = g_occraw[base + px];
        dreg[j] = d; oreg[j] = o;
        dmn = fminf(dmn, d); dmx = fmaxf(dmx, d);
        omn = fminf(omn, o); omx = fmaxf(omx, o);
        S[px] = fabsf(carrier[base + px]);
    }
#pragma unroll
    for (int off = 16; off; off >>= 1) {
        dmn = fminf(dmn, __shfl_down_sync(0xffffffffu, dmn, off));
        dmx = fmaxf(dmx, __shfl_down_sync(0xffffffffu, dmx, off));
        omn = fminf(omn, __shfl_down_sync(0xffffffffu, omn, off));
        omx = fmaxf(omx, __shfl_down_sync(0xffffffffu, omx, off));
    }
    if (!lane) { smn[warp] = dmn; smx[warp] = dmx; rv[warp] = omn; ri[warp] = __float_as_int(omx); }
    __syncthreads();
    if (tid < 32) {
        float a = smn[lane], c = smx[lane], e = rv[lane], f = __int_as_float(ri[lane]);
#pragma unroll
        for (int off = 16; off; off >>= 1) {
            a = fminf(a, __shfl_down_sync(0xffffffffu, a, off));
            c = fmaxf(c, __shfl_down_sync(0xffffffffu, c, off));
            e = fminf(e, __shfl_down_sync(0xffffffffu, e, off));
            f = fmaxf(f, __shfl_down_sync(0xffffffffu, f, off));
        }
        if (!lane) { smn[0] = a; smx[0] = c; rv[0] = e; ri[0] = __float_as_int(f); }
    }
    __syncthreads();
    dmn = smn[0]; dmx = smx[0]; omn = rv[0]; omx = __int_as_float(ri[0]);
    __syncthreads();

    float cav[9];
    float cmn = FLT_MAX, cmx = -FLT_MAX;
#pragma unroll
    for (int j = 0; j < 9; j++) {
        int px = tid + j*1024;
        int y = px / Wn, x = px - y*Wn;
        float v = win3sum_s(S, y, x) * (1.0f / 9.0f);
        cav[j] = v;
        cmn = fminf(cmn, v); cmx = fmaxf(cmx, v);
    }
#pragma unroll
    for (int off = 16; off; off >>= 1) {
        cmn = fminf(cmn, __shfl_down_sync(0xffffffffu, cmn, off));
        cmx = fmaxf(cmx, __shfl_down_sync(0xffffffffu, cmx, off));
    }
    if (!lane) { smn[warp] = cmn; smx[warp] = cmx; }
    __syncthreads();
    if (tid < 32) {
        float a = smn[lane], c = smx[lane];
#pragma unroll
        for (int off = 16; off; off >>= 1) {
            a = fminf(a, __shfl_down_sync(0xffffffffu, a, off));
            c = fmaxf(c, __shfl_down_sync(0xffffffffu, c, off));
        }
        if (!lane) { smn[0] = a; smx[0] = c; }
    }
    __syncthreads();
    cmn = smn[0]; cmx = smx[0];

    float dinv = 1.0f / fmaxf(dmx - dmn, 1e-6f);
    float oinv = 1.0f / fmaxf(omx - omn, 1e-6f);
    float cinv = 1.0f / fmaxf(cmx - cmn, 1e-6f);

    float occ[9], mval[9];
#pragma unroll
    for (int j = 0; j < 9; j++) {
        int px = tid + j*1024;
        float dn = (dreg[j] - dmn) * dinv;
        float oc = (oreg[j] - omn) * oinv;
        float cs = (cav[j] - cmn) * cinv;
        g_dnorm[base + px] = dn;
        g_occ[base + px] = oc;
        occ[j] = oc;
        float ev = 0.8f * cs + 0.2f * dn;
        mval[j] = (ev >= 0.28f) ? 1.0f : 0.0f;
    }
    __syncthreads();
#pragma unroll
    for (int j = 0; j < 9; j++) S[tid + j*1024] = mval[j];
    __syncthreads();
    float er[9];
#pragma unroll
    for (int j = 0; j < 9; j++) {
        int px = tid + j*1024;
        er[j] = win3min_s(S, px / Wn, px % Wn);
    }
    __syncthreads();
#pragma unroll
    for (int j = 0; j < 9; j++) S[tid + j*1024] = er[j];
    __syncthreads();
    float op[9];
#pragma unroll
    for (int j = 0; j < 9; j++) {
        int px = tid + j*1024;
        op[j] = fminf(fmaxf(win3max_s(S, px / Wn, px % Wn), 0.0f), 1.0f);
    }
    __syncthreads();
#pragma unroll
    for (int j = 0; j < 9; j++) S[tid + j*1024] = op[j];
    __syncthreads();
    float sc[9];
#pragma unroll
    for (int j = 0; j < 9; j++) {
        int px = tid + j*1024;
        float sp = fminf(fmaxf(win3max_s(S, px / Wn, px % Wn), 0.0f), 1.0f);
        g_sup[base + px] = sp;
        sc[j] = occ[j] * sp;
    }
    __syncthreads();
#pragma unroll
    for (int j = 0; j < 9; j++) S[tid + j*1024] = sc[j];
    __syncthreads();
    float masked[9];
#pragma unroll
    for (int j = 0; j < 9; j++) {
        int px = tid + j*1024;
        float lm = win3max_s(S, px / Wn, px % Wn);
        masked[j] = (sc[j] >= lm && sc[j] > 0.05f) ? sc[j] : 0.0f;
        g_anch[base + px] = 0.0f;
    }
    __syncthreads();

    for (int k = 0; k < TOPKn; k++) {
        float v = -FLT_MAX; int bi = 0x7fffffff;
#pragma unroll
        for (int j = 0; j < 9; j++) {
            float m = masked[j]; int ix = tid + j*1024;
            if (m > v || (m == v && ix < bi)) { v = m; bi = ix; }
        }
#pragma unroll
        for (int off = 16; off; off >>= 1) {
            float ov = __shfl_down_sync(0xffffffffu, v, off);
            int   oi = __shfl_down_sync(0xffffffffu, bi, off);
            if (ov > v || (ov == v && oi < bi)) { v = ov; bi = oi; }
        }
        if (!lane) { rv[warp] = v; ri[warp] = bi; }
        __syncthreads();
        if (tid < 32) {
            v = rv[lane]; bi = ri[lane];
#pragma unroll
            for (int off = 16; off; off >>= 1) {
                float ov = __shfl_down_sync(0xffffffffu, v, off);
                int   oi = __shfl_down_sync(0xffffffffu, bi, off);
                if (ov > v || (ov == v && oi < bi)) { v = ov; bi = oi; }
            }
            if (!lane) { s_val[k] = v; s_idx[k] = bi; s_bi = bi; }
        }
        __syncthreads();
        int win = s_bi;
        if ((win & 1023) == tid) masked[win >> 10] = -FLT_MAX;
    }
    __syncthreads();

    if (tid < TOPKn) {
        float v = s_val[tid];
        int   ix = s_idx[tid];
        g_anch[base + ix] = v;
        float f[Rn];
#pragma unroll
        for (int r = 0; r < Rn; r++)
            f[r] = g_proj[((size_t)b*Rn + r) * HWn + ix];
        float best = -FLT_MAX; int bp = 0;
#pragma unroll
        for (int p = 0; p < Pn; p++) {
            float l = 0.0f;
#pragma unroll
            for (int r = 0; r < Rn; r++) l += f[r] * sprot[p*Rn + r];
            if (l > best) { best = l; bp = p; }
        }
        spidx[tid] = bp;
    }
    __syncthreads();

    // ---- stamping (merged): 24 anchors x 169 px, 12 channels each ----
    for (int wk = tid; wk < TOPKn * KSn * KSn; wk += 1024) {
        int a = wk / (KSn*KSn);
        int t = wk - a * (KSn*KSn);
        float val = s_val[a];
        if (val <= 0.0f) continue;
        int idx = s_idx[a];
        int pi  = spidx[a];
        int ys = idx / Wn, xs = idx % Wn;
        int dy = t / KSn, dx = t % KSn;
        int y = ys + dy - KSn/2, x = xs + dx - KSn/2;
        if (y < 0 || y >= Hn || x < 0 || x >= Wn) continue;
        float gx  = (float)(-1.0 + (double)dx * (2.0 / 12.0));
        float gy  = (float)(-1.0 + (double)dy * (2.0 / 12.0));
        float ori = (float)((double)pi * (3.14159265358979323846 / 16.0));
        float ln  = c_lenL[pi & 3];
        float wd  = c_widL[(pi >> 2) & 3];
        float c = cosf(ori), s = sinf(ori);
        float xr =  c * gx + s * gy;
        float yr = -s * gx + c * gy;
        float txx = xr / ln, tyy = yr / wd;
        float foot = expf(-(txx*txx) - (tyy*tyy)) * val;
        float* cv = g_canvas + (size_t)b * Rn * HWn + y*Wn + x;
#pragma unroll
        for (int r = 0; r < Rn; r++)
            atomicAdd(cv + (size_t)r * HWn, sprot[pi*Rn + r] * foot);
    }
}

// ---------------- final: (16->12 gelu)->(12->768), f-split x2 ----------------
__global__ void __launch_bounds__(128) k_final(const float* __restrict__ w3,
                                               const float* __restrict__ b3,
                                               const float* __restrict__ w4,
                                               const float* __restrict__ b4,
                                               float* __restrict__ outp) {
    __shared__ __align__(16) ull wint[192*12];  // [(local f-pair)][r] = (w4[2fp][r], w4[2fp+1][r])
    __shared__ ull bp4[192];
    __shared__ float sw3[Rn*16];
    __shared__ float sb3[Rn];

    int bx = blockIdx.x;
    int fh = bx & 1;                 // which 384-channel half
    int t2 = bx >> 1;
    int b  = t2 / 36;
    int f0 = fh * 384;
    {
        float* wf = (float*)wint;
        for (int i = threadIdx.x; i < 384*Rn; i += 128) {
            int fl = i / Rn, r = i - fl*Rn;
            wf[(fl >> 1)*24 + r*2 + (fl & 1)] = w4[(f0 + fl)*Rn + r];
        }
        float* bf = (float*)bp4;
        for (int i = threadIdx.x; i < 384; i += 128) bf[i] = b4[f0 + i];
        for (int i = threadIdx.x; i < Rn*16; i += 128) sw3[i] = w3[i];
        for (int i = threadIdx.x; i < Rn;    i += 128) sb3[i] = b3[i];
    }
    __syncthreads();

    int p0 = (t2 % 36) * 256 + threadIdx.x * 2;
    size_t bpx = (size_t)b * HWn + p0;

    float2 sup = *(const float2*)(g_sup + bpx);
    float2 occ = *(const float2*)(g_occ + bpx);
    float2 an  = *(const float2*)(g_anch + bpx);
    float2 dn  = *(const float2*)(g_dnorm + bpx);

    float in0[16], in1[16];
#pragma unroll
    for (int r = 0; r < Rn; r++) {
        float2 cv = *(const float2*)(g_canvas + ((size_t)b*Rn + r) * HWn + p0);
        in0[r] = cv.x * sup.x;
        in1[r] = cv.y * sup.y;
    }
    in0[12] = occ.x; in1[12] = occ.y;
    in0[13] = sup.x; in1[13] = sup.y;
    in0[14] = an.x;  in1[14] = an.y;
    in0[15] = dn.x;  in1[15] = dn.y;

    ull md0[Rn], md1[Rn];
#pragma unroll
    for (int r = 0; r < Rn; r++) {
        float m0 = sb3[r], m1 = sb3[r];
#pragma unroll
        for (int j = 0; j < 16; j++) {
            float w = sw3[r*16 + j];
            m0 += in0[j] * w;
            m1 += in1[j] * w;
        }
        md0[r] = dup2(gelu_exact(m0));
        md1[r] = dup2(gelu_exact(m1));
    }

    float* ob = outp + (size_t)b * FCn * HWn + (size_t)f0 * HWn + p0;
    const ulonglong2* wv = (const ulonglong2*)wint;
#pragma unroll 2
    for (int fp = 0; fp < 192; fp++) {
        ull a0 = bp4[fp];
        ull a1 = a0;
        const ulonglong2* w = wv + fp*6;
#pragma unroll
        for (int q = 0; q < 6; q++) {
            ulonglong2 wq = w[q];
            ffma2(a0, md0[2*q],     wq.x);
            ffma2(a1, md1[2*q],     wq.x);
            ffma2(a0, md0[2*q + 1], wq.y);
            ffma2(a1, md1[2*q + 1], wq.y);
        }
        float2 u0 = unpack2(a0), u1 = unpack2(a1);
        float2 v0; v0.x = u0.x; v0.y = u1.x;
        float2 v1; v1.x = u0.y; v1.y = u1.y;
        *(float2*)(ob + (size_t)(2*fp)     * HWn) = v0;
        *(float2*)(ob + (size_t)(2*fp + 1) * HWn) = v1;
    }
}

// ---------------- launch ----------------
extern "C" void kernel_launch(void* const* d_in, const int* in_sizes, int n_in,
                              void* d_out, int out_size) {
    const float* features = (const float*)d_in[0];
    const float* carrier  = (const float*)d_in[1];
    const float* density  = (const float*)d_in[2];
    const float* w1 = (const float*)d_in[3];
    const float* b1 = (const float*)d_in[4];
    const float* w2 = (const float*)d_in[5];
    const float* b2 = (const float*)d_in[6];
    const float* w3 = (const float*)d_in[7];
    const float* b3 = (const float*)d_in[8];
    const float* w4 = (const float*)d_in[9];
    const float* b4 = (const float*)d_in[10];
    const float* proto = (const float*)d_in[11];
    float* outp = (float*)d_out;

    k_conv1<<<288, 256>>>(features, w1, b1);
    k_conv2<<<dim3(6, 6, 8), 256>>>(w2, b2);
    k_fused<<<Bn, 1024>>>(carrier, density, proto);
    k_final<<<576, 128>>>(w3, b3, w4, b4, outp);
}